// round 3
// baseline (speedup 1.0000x reference)
#include <cuda_runtime.h>
#include <cuda_bf16.h>
#include <math.h>

// ---------------- GPT-2 small config ----------------
#define LAYERS 12
#define NH     12
#define C      768
#define HD     64
#define TSEQ   1024
#define BATCH  2
#define NTOK   (BATCH * TSEQ)      // 2048
#define VOCAB  50257
#define C3     (3 * C)             // 2304
#define C4     (4 * C)             // 3072

// ---------------- scratch (static __device__, no allocation) ----------------
__device__ float g_x  [NTOK * C];    // residual stream
__device__ float g_ln [NTOK * C];    // layernorm output
__device__ float g_qkv[NTOK * C3];   // qkv projection
__device__ float g_att[NTOK * C];    // attention output
__device__ float g_h  [NTOK * C4];   // MLP hidden

// ---------------- embedding ----------------
__global__ void embed_kernel(const int* __restrict__ idx,
                             const float* __restrict__ wte,
                             const float* __restrict__ wpe,
                             float* __restrict__ x) {
    int i = blockIdx.x * blockDim.x + threadIdx.x;
    if (i >= NTOK * C) return;
    int c  = i % C;
    int bt = i / C;
    int t  = bt % TSEQ;
    x[i] = wte[(size_t)idx[bt] * C + c] + wpe[(size_t)t * C + c];
}

// ---------------- layernorm (1 block = 1 row of 768) ----------------
__global__ void ln_kernel(const float* __restrict__ in,
                          const float* __restrict__ w,
                          const float* __restrict__ b,
                          float* __restrict__ out) {
    int row = blockIdx.x;
    int tid = threadIdx.x;                 // 256 threads
    const float* p = in + (size_t)row * C;

    float v[3];
    float s1 = 0.f, s2 = 0.f;
#pragma unroll
    for (int i = 0; i < 3; ++i) {
        v[i] = p[tid + i * 256];
        s1 += v[i];
        s2 += v[i] * v[i];
    }
#pragma unroll
    for (int o = 16; o > 0; o >>= 1) {
        s1 += __shfl_xor_sync(0xFFFFFFFFu, s1, o);
        s2 += __shfl_xor_sync(0xFFFFFFFFu, s2, o);
    }
    __shared__ float r1[8], r2[8];
    __shared__ float s_mu, s_rstd;
    int lane = tid & 31, warp = tid >> 5;
    if (lane == 0) { r1[warp] = s1; r2[warp] = s2; }
    __syncthreads();
    if (tid == 0) {
        float a = 0.f, q = 0.f;
#pragma unroll
        for (int i = 0; i < 8; ++i) { a += r1[i]; q += r2[i]; }
        float mu  = a / (float)C;
        float var = q / (float)C - mu * mu;
        s_mu   = mu;
        s_rstd = rsqrtf(var + 1e-5f);
    }
    __syncthreads();
    float mu = s_mu, rstd = s_rstd;
    float* o = out + (size_t)row * C;
#pragma unroll
    for (int i = 0; i < 3; ++i) {
        int c = tid + i * 256;
        o[c] = (v[i] - mu) * rstd * w[c] + b[c];
    }
}

// ---------------- GEMM: out[M,N] = A[M,K] @ W[K,N] (+bias) (+epi) ----------------
// epi: 0 = none, 1 = tanh-GELU, 2 = add residual res[M,N]
#define BM 128
#define BN 128
#define BK 16

__global__ __launch_bounds__(256, 2) void gemm_kernel(
    const float* __restrict__ A, const float* __restrict__ W,
    const float* __restrict__ bias, const float* __restrict__ res,
    float* __restrict__ out, int M, int N, int K, int epi)
{
    __shared__ float As[BK][BM];
    __shared__ float Bs[BK][BN];

    int tid = threadIdx.x;
    int m0 = blockIdx.y * BM;
    int n0 = blockIdx.x * BN;
    int tx = tid & 15;        // 16 cols of 8
    int ty = tid >> 4;        // 16 rows of 8

    float acc[8][8] = {};

    int arow = tid >> 1;            // 0..127
    int ac8  = (tid & 1) * 8;       // 0 or 8 (K offset; K % 16 == 0 always)

    for (int k0 = 0; k0 < K; k0 += BK) {
        // A tile: 128 rows x 16 cols, two float4 per thread
        const float* ap = A + (size_t)(m0 + arow) * K + k0 + ac8;
        float4 av0 = *(const float4*)(ap);
        float4 av1 = *(const float4*)(ap + 4);
        As[ac8 + 0][arow] = av0.x;
        As[ac8 + 1][arow] = av0.y;
        As[ac8 + 2][arow] = av0.z;
        As[ac8 + 3][arow] = av0.w;
        As[ac8 + 4][arow] = av1.x;
        As[ac8 + 5][arow] = av1.y;
        As[ac8 + 6][arow] = av1.z;
        As[ac8 + 7][arow] = av1.w;
        // B tile: 16 rows x 128 cols, 8 scalars per thread (N tail guarded)
#pragma unroll
        for (int i = 0; i < 8; ++i) {
            int idx = tid + i * 256;
            int br = idx >> 7, bc = idx & 127;
            int n = n0 + bc;
            Bs[br][bc] = (n < N) ? W[(size_t)(k0 + br) * N + n] : 0.f;
        }
        __syncthreads();
#pragma unroll
        for (int kk = 0; kk < BK; ++kk) {
            float4 a0 = *(const float4*)&As[kk][ty * 8];
            float4 a1 = *(const float4*)&As[kk][ty * 8 + 4];
            float4 b0 = *(const float4*)&Bs[kk][tx * 8];
            float4 b1 = *(const float4*)&Bs[kk][tx * 8 + 4];
            float a[8] = {a0.x, a0.y, a0.z, a0.w, a1.x, a1.y, a1.z, a1.w};
            float b[8] = {b0.x, b0.y, b0.z, b0.w, b1.x, b1.y, b1.z, b1.w};
#pragma unroll
            for (int i = 0; i < 8; ++i)
#pragma unroll
                for (int j = 0; j < 8; ++j)
                    acc[i][j] += a[i] * b[j];
        }
        __syncthreads();
    }

#pragma unroll
    for (int i = 0; i < 8; ++i) {
        int m = m0 + ty * 8 + i;
#pragma unroll
        for (int j = 0; j < 8; ++j) {
            int n = n0 + tx * 8 + j;
            if (n < N) {
                float v = acc[i][j] + (bias ? bias[n] : 0.f);
                if (epi == 1) {
                    v = 0.5f * v * (1.f + tanhf(0.7978845608028654f * (v + 0.044715f * v * v * v)));
                } else if (epi == 2) {
                    v += res[(size_t)m * N + n];
                }
                out[(size_t)m * N + n] = v;
            }
        }
    }
}

// ---------------- causal attention, warp per query ----------------
__global__ void attn_kernel(const float* __restrict__ qkv, float* __restrict__ out) {
    int warp = threadIdx.x >> 5;
    int lane = threadIdx.x & 31;
    int q  = blockIdx.x * 4 + warp;     // 0..1023
    int bh = blockIdx.y;
    int b  = bh / NH, h = bh % NH;

    const float* qp = qkv + ((size_t)(b * TSEQ + q) * C3) + h * HD;
    float2 qv = *(const float2*)(qp + lane * 2);

    float m = -1e30f, l = 0.f, acc0 = 0.f, acc1 = 0.f;
    for (int t = 0; t <= q; ++t) {
        const float* kp = qkv + ((size_t)(b * TSEQ + t) * C3) + C + h * HD;
        float2 kv = *(const float2*)(kp + lane * 2);
        float s = qv.x * kv.x + qv.y * kv.y;
#pragma unroll
        for (int o = 16; o > 0; o >>= 1)
            s += __shfl_xor_sync(0xFFFFFFFFu, s, o);
        s *= 0.125f;                                  // 1/sqrt(64)
        float2 vv = *(const float2*)(kp + C + lane * 2);
        float mn = fmaxf(m, s);
        float alpha = __expf(m - mn);
        float p = __expf(s - mn);
        l    = l * alpha + p;
        acc0 = acc0 * alpha + p * vv.x;
        acc1 = acc1 * alpha + p * vv.y;
        m = mn;
    }
    float inv = 1.f / l;
    float* op = out + ((size_t)(b * TSEQ + q) * C) + h * HD;
    op[lane * 2 + 0] = acc0 * inv;
    op[lane * 2 + 1] = acc1 * inv;
}

// ---------------- launch ----------------
extern "C" void kernel_launch(void* const* d_in, const int* in_sizes, int n_in,
                              void* d_out, int out_size) {
    const int*   idx      = (const int*)  d_in[0];
    const float* wte      = (const float*)d_in[1];
    const float* wpe      = (const float*)d_in[2];
    const float* ln1_w    = (const float*)d_in[3];
    const float* ln1_b    = (const float*)d_in[4];
    const float* attn_w   = (const float*)d_in[5];
    const float* attn_b   = (const float*)d_in[6];
    const float* proj_w   = (const float*)d_in[7];
    const float* proj_b   = (const float*)d_in[8];
    const float* ln2_w    = (const float*)d_in[9];
    const float* ln2_b    = (const float*)d_in[10];
    const float* fc_w     = (const float*)d_in[11];
    const float* fc_b     = (const float*)d_in[12];
    const float* fcproj_w = (const float*)d_in[13];
    const float* fcproj_b = (const float*)d_in[14];
    const float* lnf_w    = (const float*)d_in[15];
    const float* lnf_b    = (const float*)d_in[16];
    const float* lm_head  = (const float*)d_in[17];
    float* out = (float*)d_out;

    float *x, *ln, *qkv, *att, *h;
    cudaGetSymbolAddress((void**)&x,   g_x);
    cudaGetSymbolAddress((void**)&ln,  g_ln);
    cudaGetSymbolAddress((void**)&qkv, g_qkv);
    cudaGetSymbolAddress((void**)&att, g_att);
    cudaGetSymbolAddress((void**)&h,   g_h);

    embed_kernel<<<(NTOK * C + 255) / 256, 256>>>(idx, wte, wpe, x);

    for (int l = 0; l < LAYERS; ++l) {
        // ln1 -> qkv -> attention -> proj (+residual)
        ln_kernel<<<NTOK, 256>>>(x, ln1_w + l * C, ln1_b + l * C, ln);
        gemm_kernel<<<dim3(C3 / BN, NTOK / BM), 256>>>(
            ln, attn_w + (size_t)l * C * C3, attn_b + (size_t)l * C3,
            nullptr, qkv, NTOK, C3, C, 0);
        attn_kernel<<<dim3(TSEQ / 4, BATCH * NH), 128>>>(qkv, att);
        gemm_kernel<<<dim3(C / BN, NTOK / BM), 256>>>(
            att, proj_w + (size_t)l * C * C, proj_b + (size_t)l * C,
            x, x, NTOK, C, C, 2);
        // ln2 -> fc (+gelu) -> fcproj (+residual)
        ln_kernel<<<NTOK, 256>>>(x, ln2_w + l * C, ln2_b + l * C, ln);
        gemm_kernel<<<dim3(C4 / BN, NTOK / BM), 256>>>(
            ln, fc_w + (size_t)l * C * C4, fc_b + (size_t)l * C4,
            nullptr, h, NTOK, C4, C, 1);
        gemm_kernel<<<dim3(C / BN, NTOK / BM), 256>>>(
            h, fcproj_w + (size_t)l * C4 * C, fcproj_b + (size_t)l * C,
            x, x, NTOK, C, C4, 2);
    }

    // final LN + lm_head
    ln_kernel<<<NTOK, 256>>>(x, lnf_w, lnf_b, ln);
    gemm_kernel<<<dim3((VOCAB + BN - 1) / BN, NTOK / BM), 256>>>(
        ln, lm_head, nullptr, nullptr, out, NTOK, VOCAB, C, 0);
}

// round 4
// speedup vs baseline: 1.2025x; 1.2025x over previous
#include <cuda_runtime.h>
#include <cuda_bf16.h>
#include <math.h>

// ---------------- GPT-2 small config ----------------
#define LAYERS 12
#define NH     12
#define C      768
#define HD     64
#define TSEQ   1024
#define BATCH  2
#define NTOK   (BATCH * TSEQ)      // 2048
#define VOCAB  50257
#define C3     (3 * C)             // 2304
#define C4     (4 * C)             // 3072

typedef unsigned long long ull;

// ---------------- packed fp32x2 helpers (sm_103a FFMA2 path) ----------------
__device__ __forceinline__ ull fma2(ull a, ull b, ull c) {
    ull d;
    asm("fma.rn.f32x2 %0, %1, %2, %3;" : "=l"(d) : "l"(a), "l"(b), "l"(c));
    return d;
}
__device__ __forceinline__ ull mul2(ull a, ull b) {
    ull d;
    asm("mul.rn.f32x2 %0, %1, %2;" : "=l"(d) : "l"(a), "l"(b));
    return d;
}
__device__ __forceinline__ ull pack2(float lo, float hi) {
    ull d;
    asm("mov.b64 %0, {%1, %2};" : "=l"(d) : "r"(__float_as_uint(lo)), "r"(__float_as_uint(hi)));
    return d;
}
__device__ __forceinline__ float2 unpack2(ull v) {
    unsigned lo, hi;
    asm("mov.b64 {%0, %1}, %2;" : "=r"(lo), "=r"(hi) : "l"(v));
    return make_float2(__uint_as_float(lo), __uint_as_float(hi));
}

// ---------------- scratch (static __device__, no allocation) ----------------
__device__ float g_x  [NTOK * C];    // residual stream
__device__ float g_ln [NTOK * C];    // layernorm output
__device__ float g_qkv[NTOK * C3];   // qkv projection
__device__ float g_att[NTOK * C];    // attention output
__device__ float g_h  [NTOK * C4];   // MLP hidden

// ---------------- embedding ----------------
__global__ void embed_kernel(const int* __restrict__ idx,
                             const float* __restrict__ wte,
                             const float* __restrict__ wpe,
                             float* __restrict__ x) {
    int i = blockIdx.x * blockDim.x + threadIdx.x;
    if (i >= NTOK * C) return;
    int c  = i % C;
    int bt = i / C;
    int t  = bt % TSEQ;
    x[i] = wte[(size_t)idx[bt] * C + c] + wpe[(size_t)t * C + c];
}

// ---------------- layernorm (1 block = 1 row of 768) ----------------
__global__ void ln_kernel(const float* __restrict__ in,
                          const float* __restrict__ w,
                          const float* __restrict__ b,
                          float* __restrict__ out) {
    int row = blockIdx.x;
    int tid = threadIdx.x;                 // 256 threads
    const float* p = in + (size_t)row * C;

    float v[3];
    float s1 = 0.f, s2 = 0.f;
#pragma unroll
    for (int i = 0; i < 3; ++i) {
        v[i] = p[tid + i * 256];
        s1 += v[i];
        s2 += v[i] * v[i];
    }
#pragma unroll
    for (int o = 16; o > 0; o >>= 1) {
        s1 += __shfl_xor_sync(0xFFFFFFFFu, s1, o);
        s2 += __shfl_xor_sync(0xFFFFFFFFu, s2, o);
    }
    __shared__ float r1[8], r2[8];
    __shared__ float s_mu, s_rstd;
    int lane = tid & 31, warp = tid >> 5;
    if (lane == 0) { r1[warp] = s1; r2[warp] = s2; }
    __syncthreads();
    if (tid == 0) {
        float a = 0.f, q = 0.f;
#pragma unroll
        for (int i = 0; i < 8; ++i) { a += r1[i]; q += r2[i]; }
        float mu  = a / (float)C;
        float var = q / (float)C - mu * mu;
        s_mu   = mu;
        s_rstd = rsqrtf(var + 1e-5f);
    }
    __syncthreads();
    float mu = s_mu, rstd = s_rstd;
    float* o = out + (size_t)row * C;
#pragma unroll
    for (int i = 0; i < 3; ++i) {
        int c = tid + i * 256;
        o[c] = (v[i] - mu) * rstd * w[c] + b[c];
    }
}

// ---------------- GEMM: out[M,N] = A[M,K] @ W[K,N] (+bias) (+epi) ----------------
// epi: 0 = none, 1 = tanh-GELU, 2 = add residual res[M,N]
// Inner product uses packed fp32x2 FMA (FFMA2): acc packed along N (pairs of
// adjacent columns), B pairs read packed directly from smem, A duplicated.
#define BM 128
#define BN 128
#define BK 16

__global__ __launch_bounds__(256, 2) void gemm_kernel(
    const float* __restrict__ A, const float* __restrict__ W,
    const float* __restrict__ bias, const float* __restrict__ res,
    float* __restrict__ out, int M, int N, int K, int epi)
{
    __shared__ float As[BK][BM];
    __shared__ float Bs[BK][BN];

    int tid = threadIdx.x;
    int m0 = blockIdx.y * BM;
    int n0 = blockIdx.x * BN;
    int tx = tid & 15;        // 16 cols of 8
    int ty = tid >> 4;        // 16 rows of 8

    ull acc2[8][4];
#pragma unroll
    for (int i = 0; i < 8; ++i)
#pragma unroll
        for (int j = 0; j < 4; ++j) acc2[i][j] = 0ULL;  // bit pattern (0.f,0.f)

    int arow = tid >> 1;            // 0..127
    int ac8  = (tid & 1) * 8;       // 0 or 8 (K offset; K % 16 == 0 always)

    for (int k0 = 0; k0 < K; k0 += BK) {
        // A tile: 128 rows x 16 cols, two float4 per thread
        const float* ap = A + (size_t)(m0 + arow) * K + k0 + ac8;
        float4 av0 = *(const float4*)(ap);
        float4 av1 = *(const float4*)(ap + 4);
        As[ac8 + 0][arow] = av0.x;
        As[ac8 + 1][arow] = av0.y;
        As[ac8 + 2][arow] = av0.z;
        As[ac8 + 3][arow] = av0.w;
        As[ac8 + 4][arow] = av1.x;
        As[ac8 + 5][arow] = av1.y;
        As[ac8 + 6][arow] = av1.z;
        As[ac8 + 7][arow] = av1.w;
        // B tile: 16 rows x 128 cols, 8 scalars per thread (N tail guarded)
#pragma unroll
        for (int i = 0; i < 8; ++i) {
            int idx = tid + i * 256;
            int br = idx >> 7, bc = idx & 127;
            int n = n0 + bc;
            Bs[br][bc] = (n < N) ? W[(size_t)(k0 + br) * N + n] : 0.f;
        }
        __syncthreads();
#pragma unroll
        for (int kk = 0; kk < BK; ++kk) {
            float4 a0 = *(const float4*)&As[kk][ty * 8];
            float4 a1 = *(const float4*)&As[kk][ty * 8 + 4];
            ulonglong2 bA = *(const ulonglong2*)&Bs[kk][tx * 8];
            ulonglong2 bB = *(const ulonglong2*)&Bs[kk][tx * 8 + 4];
            ull b2[4] = {bA.x, bA.y, bB.x, bB.y};
            float a[8] = {a0.x, a0.y, a0.z, a0.w, a1.x, a1.y, a1.z, a1.w};
#pragma unroll
            for (int i = 0; i < 8; ++i) {
                ull ai = pack2(a[i], a[i]);
#pragma unroll
                for (int j = 0; j < 4; ++j)
                    acc2[i][j] = fma2(ai, b2[j], acc2[i][j]);
            }
        }
        __syncthreads();
    }

#pragma unroll
    for (int i = 0; i < 8; ++i) {
        int m = m0 + ty * 8 + i;
#pragma unroll
        for (int j = 0; j < 4; ++j) {
            float2 u = unpack2(acc2[i][j]);
            float vv[2] = {u.x, u.y};
#pragma unroll
            for (int s = 0; s < 2; ++s) {
                int n = n0 + tx * 8 + j * 2 + s;
                if (n < N) {
                    float v = vv[s] + (bias ? bias[n] : 0.f);
                    if (epi == 1) {
                        v = 0.5f * v * (1.f + tanhf(0.7978845608028654f * (v + 0.044715f * v * v * v)));
                    } else if (epi == 2) {
                        v += res[(size_t)m * N + n];
                    }
                    out[(size_t)m * N + n] = v;
                }
            }
        }
    }
}

// ---------------- causal attention: thread per query, smem K/V tiles ----------------
#define QT 128     // queries per block (== threads per block)
#define KT 16      // keys per smem tile

__global__ __launch_bounds__(QT) void attn_kernel(const float* __restrict__ qkv,
                                                  float* __restrict__ out) {
    __shared__ float Ks[KT][HD];
    __shared__ float Vs[KT][HD];

    int tid = threadIdx.x;
    int qt  = gridDim.x - 1 - blockIdx.x;   // heaviest q-tiles first
    int q   = qt * QT + tid;
    int bh  = blockIdx.y;
    int b   = bh / NH, h = bh % NH;

    const float* base = qkv + (size_t)b * TSEQ * C3 + h * HD;

    // load this thread's query row (scaled by 1/sqrt(HD) up front)
    ull q2[HD / 2];
    {
        const ulonglong2* qp = (const ulonglong2*)(base + (size_t)q * C3);
        ull scale = pack2(0.125f, 0.125f);
#pragma unroll
        for (int i = 0; i < HD / 4; ++i) {
            ulonglong2 v = qp[i];
            q2[2 * i + 0] = mul2(v.x, scale);
            q2[2 * i + 1] = mul2(v.y, scale);
        }
    }

    ull acc2[HD / 2];
#pragma unroll
    for (int i = 0; i < HD / 2; ++i) acc2[i] = 0ULL;
    float m = -3e38f, l = 0.f;

    int ntiles = (qt * QT + QT - 1) / KT + 1;   // tiles covering keys 0..block_max_q
    for (int t = 0; t < ntiles; ++t) {
        int k0 = t * KT;
        __syncthreads();
        // cooperative K/V tile load: KT*HD = 1024 floats each = 256 float4
#pragma unroll
        for (int i = 0; i < (KT * HD / 4) / QT; ++i) {
            int idx = tid + i * QT;              // 0..255
            int k  = idx >> 4;                   // 16 float4 per row
            int d4 = (idx & 15) * 4;
            const float* row = base + (size_t)(k0 + k) * C3;
            *(float4*)&Ks[k][d4] = *(const float4*)(row + C + d4);
            *(float4*)&Vs[k][d4] = *(const float4*)(row + 2 * C + d4);
        }
        __syncthreads();

        // phase 1: scores for this tile (packed dot products, smem broadcast)
        float s[KT];
#pragma unroll
        for (int k = 0; k < KT; ++k) {
            const ulonglong2* kp = (const ulonglong2*)&Ks[k][0];
            ull sa = 0ULL, sb = 0ULL;
#pragma unroll
            for (int d = 0; d < HD / 4; ++d) {
                ulonglong2 kv = kp[d];
                sa = fma2(q2[2 * d + 0], kv.x, sa);
                sb = fma2(q2[2 * d + 1], kv.y, sb);
            }
            float2 ua = unpack2(sa);
            float2 ub = unpack2(sb);
            s[k] = (ua.x + ua.y) + (ub.x + ub.y);
        }

        // phase 2: online softmax update (one rescale per tile)
        float mt = -3e38f;
#pragma unroll
        for (int k = 0; k < KT; ++k)
            if (k0 + k <= q) mt = fmaxf(mt, s[k]);
        float mn = fmaxf(m, mt);
        float alpha = __expf(m - mn);
        ull al2 = pack2(alpha, alpha);
#pragma unroll
        for (int d = 0; d < HD / 2; ++d) acc2[d] = mul2(acc2[d], al2);
        l *= alpha;
#pragma unroll
        for (int k = 0; k < KT; ++k) {
            float p = (k0 + k <= q) ? __expf(s[k] - mn) : 0.f;
            l += p;
            ull p2 = pack2(p, p);
            const ulonglong2* vp = (const ulonglong2*)&Vs[k][0];
#pragma unroll
            for (int d = 0; d < HD / 4; ++d) {
                ulonglong2 vv = vp[d];
                acc2[2 * d + 0] = fma2(p2, vv.x, acc2[2 * d + 0]);
                acc2[2 * d + 1] = fma2(p2, vv.y, acc2[2 * d + 1]);
            }
        }
        m = mn;
    }

    float inv = 1.f / l;
    ull inv2 = pack2(inv, inv);
    ull* op = (ull*)(out + (size_t)(b * TSEQ + q) * C + h * HD);
#pragma unroll
    for (int d = 0; d < HD / 2; ++d) op[d] = mul2(acc2[d], inv2);
}

// ---------------- launch ----------------
extern "C" void kernel_launch(void* const* d_in, const int* in_sizes, int n_in,
                              void* d_out, int out_size) {
    const int*   idx      = (const int*)  d_in[0];
    const float* wte      = (const float*)d_in[1];
    const float* wpe      = (const float*)d_in[2];
    const float* ln1_w    = (const float*)d_in[3];
    const float* ln1_b    = (const float*)d_in[4];
    const float* attn_w   = (const float*)d_in[5];
    const float* attn_b   = (const float*)d_in[6];
    const float* proj_w   = (const float*)d_in[7];
    const float* proj_b   = (const float*)d_in[8];
    const float* ln2_w    = (const float*)d_in[9];
    const float* ln2_b    = (const float*)d_in[10];
    const float* fc_w     = (const float*)d_in[11];
    const float* fc_b     = (const float*)d_in[12];
    const float* fcproj_w = (const float*)d_in[13];
    const float* fcproj_b = (const float*)d_in[14];
    const float* lnf_w    = (const float*)d_in[15];
    const float* lnf_b    = (const float*)d_in[16];
    const float* lm_head  = (const float*)d_in[17];
    float* out = (float*)d_out;

    float *x, *ln, *qkv, *att, *h;
    cudaGetSymbolAddress((void**)&x,   g_x);
    cudaGetSymbolAddress((void**)&ln,  g_ln);
    cudaGetSymbolAddress((void**)&qkv, g_qkv);
    cudaGetSymbolAddress((void**)&att, g_att);
    cudaGetSymbolAddress((void**)&h,   g_h);

    embed_kernel<<<(NTOK * C + 255) / 256, 256>>>(idx, wte, wpe, x);

    for (int l = 0; l < LAYERS; ++l) {
        // ln1 -> qkv -> attention -> proj (+residual)
        ln_kernel<<<NTOK, 256>>>(x, ln1_w + l * C, ln1_b + l * C, ln);
        gemm_kernel<<<dim3(C3 / BN, NTOK / BM), 256>>>(
            ln, attn_w + (size_t)l * C * C3, attn_b + (size_t)l * C3,
            nullptr, qkv, NTOK, C3, C, 0);
        attn_kernel<<<dim3(TSEQ / QT, BATCH * NH), QT>>>(qkv, att);
        gemm_kernel<<<dim3(C / BN, NTOK / BM), 256>>>(
            att, proj_w + (size_t)l * C * C, proj_b + (size_t)l * C,
            x, x, NTOK, C, C, 2);
        // ln2 -> fc (+gelu) -> fcproj (+residual)
        ln_kernel<<<NTOK, 256>>>(x, ln2_w + l * C, ln2_b + l * C, ln);
        gemm_kernel<<<dim3(C4 / BN, NTOK / BM), 256>>>(
            ln, fc_w + (size_t)l * C * C4, fc_b + (size_t)l * C4,
            nullptr, h, NTOK, C4, C, 1);
        gemm_kernel<<<dim3(C / BN, NTOK / BM), 256>>>(
            h, fcproj_w + (size_t)l * C4 * C, fcproj_b + (size_t)l * C,
            x, x, NTOK, C, C4, 2);
    }

    // final LN + lm_head
    ln_kernel<<<NTOK, 256>>>(x, lnf_w, lnf_b, ln);
    gemm_kernel<<<dim3((VOCAB + BN - 1) / BN, NTOK / BM), 256>>>(
        ln, lm_head, nullptr, nullptr, out, NTOK, VOCAB, C, 0);
}

// round 8
// speedup vs baseline: 1.8786x; 1.5623x over previous
#include <cuda_runtime.h>
#include <cuda_bf16.h>
#include <math.h>
#include <stdint.h>

// ---------------- GPT-2 small config ----------------
#define LAYERS 12
#define NH     12
#define C      768
#define HD     64
#define TSEQ   1024
#define BATCH  2
#define NTOK   (BATCH * TSEQ)      // 2048
#define VOCAB  50257
#define VPAD   50304               // VOCAB padded to 128
#define C3     (3 * C)             // 2304
#define C4     (4 * C)             // 3072

typedef unsigned long long ull;

// ---------------- packed fp32x2 helpers (attention) ----------------
__device__ __forceinline__ ull fma2(ull a, ull b, ull c) {
    ull d; asm("fma.rn.f32x2 %0, %1, %2, %3;" : "=l"(d) : "l"(a), "l"(b), "l"(c)); return d;
}
__device__ __forceinline__ ull mul2(ull a, ull b) {
    ull d; asm("mul.rn.f32x2 %0, %1, %2;" : "=l"(d) : "l"(a), "l"(b)); return d;
}
__device__ __forceinline__ ull pack2(float lo, float hi) {
    ull d; asm("mov.b64 %0, {%1, %2};" : "=l"(d) : "r"(__float_as_uint(lo)), "r"(__float_as_uint(hi))); return d;
}
__device__ __forceinline__ float2 unpack2(ull v) {
    unsigned lo, hi; asm("mov.b64 {%0, %1}, %2;" : "=r"(lo), "=r"(hi) : "l"(v));
    return make_float2(__uint_as_float(lo), __uint_as_float(hi));
}

__device__ __forceinline__ uint32_t smem_u32(const void* p) {
    uint32_t a;
    asm("{ .reg .u64 t; cvta.to.shared.u64 t, %1; cvt.u32.u64 %0, t; }" : "=r"(a) : "l"(p));
    return a;
}

__device__ __forceinline__ void split_bf16(float v, __nv_bfloat16* h, __nv_bfloat16* l) {
    __nv_bfloat16 hi = __float2bfloat16(v);
    *h = hi;
    *l = __float2bfloat16(v - __bfloat162float(hi));
}

// ---------------- mma.sync helpers (sm_80+ baseline; works on plain sm_103) ----------------
__device__ __forceinline__ void ldsm_x4(uint32_t* r, uint32_t addr) {
    asm volatile("ldmatrix.sync.aligned.m8n8.x4.shared.b16 {%0,%1,%2,%3}, [%4];"
                 : "=r"(r[0]), "=r"(r[1]), "=r"(r[2]), "=r"(r[3]) : "r"(addr));
}
__device__ __forceinline__ void ldsm_x2(uint32_t* r, uint32_t addr) {
    asm volatile("ldmatrix.sync.aligned.m8n8.x2.shared.b16 {%0,%1}, [%2];"
                 : "=r"(r[0]), "=r"(r[1]) : "r"(addr));
}
__device__ __forceinline__ void mma_bf16(float* c, const uint32_t* a, const uint32_t* b) {
    asm volatile(
        "mma.sync.aligned.m16n8k16.row.col.f32.bf16.bf16.f32 "
        "{%0,%1,%2,%3}, {%4,%5,%6,%7}, {%8,%9}, {%0,%1,%2,%3};"
        : "+f"(c[0]), "+f"(c[1]), "+f"(c[2]), "+f"(c[3])
        : "r"(a[0]), "r"(a[1]), "r"(a[2]), "r"(a[3]), "r"(b[0]), "r"(b[1]));
}

// ---------------- scratch (static __device__, no allocation) ----------------
__device__ float g_x  [NTOK * C];            // residual stream (fp32)
__device__ float g_qkv[NTOK * C3];           // qkv projection (fp32)
__device__ __nv_bfloat16 g_ln_h [NTOK * C],  g_ln_l [NTOK * C];
__device__ __nv_bfloat16 g_att_h[NTOK * C],  g_att_l[NTOK * C];
__device__ __nv_bfloat16 g_h_h  [NTOK * C4], g_h_l  [NTOK * C4];
// transposed split-bf16 weights: [N, K] row-major
__device__ __nv_bfloat16 g_wqkv_h[LAYERS * C3 * C],  g_wqkv_l[LAYERS * C3 * C];
__device__ __nv_bfloat16 g_wproj_h[LAYERS * C * C],  g_wproj_l[LAYERS * C * C];
__device__ __nv_bfloat16 g_wfc_h [LAYERS * C4 * C],  g_wfc_l [LAYERS * C4 * C];
__device__ __nv_bfloat16 g_wfcp_h[LAYERS * C * C4],  g_wfcp_l[LAYERS * C * C4];
__device__ __nv_bfloat16 g_wlm_h [VPAD * C],         g_wlm_l [VPAD * C];

// ---------------- weight convert + transpose: W[L,K,N] -> Wt[L,Npad,K] split bf16 ----------------
__global__ void convw_kernel(const float* __restrict__ W,
                             __nv_bfloat16* __restrict__ Th,
                             __nv_bfloat16* __restrict__ Tl,
                             int K, int N, int Npad) {
    __shared__ float t[32][33];
    int l = blockIdx.z;
    int n0 = blockIdx.x * 32, k0 = blockIdx.y * 32;
    int tx = threadIdx.x, ty = threadIdx.y;    // 32 x 8
    const float* Wl = W + (size_t)l * K * N;
#pragma unroll
    for (int i = 0; i < 4; ++i) {
        int k = k0 + ty + i * 8;
        int n = n0 + tx;
        t[ty + i * 8][tx] = (n < N) ? Wl[(size_t)k * N + n] : 0.f;
    }
    __syncthreads();
    size_t obase = (size_t)l * Npad * K;
#pragma unroll
    for (int i = 0; i < 4; ++i) {
        int nl = ty + i * 8;
        float v = t[tx][nl];
        __nv_bfloat16 h, lo;
        split_bf16(v, &h, &lo);
        size_t o = obase + (size_t)(n0 + nl) * K + k0 + tx;
        Th[o] = h;
        Tl[o] = lo;
    }
}

// ---------------- embedding ----------------
__global__ void embed_kernel(const int* __restrict__ idx,
                             const float* __restrict__ wte,
                             const float* __restrict__ wpe,
                             float* __restrict__ x) {
    int i = blockIdx.x * blockDim.x + threadIdx.x;
    if (i >= NTOK * C) return;
    int c  = i % C;
    int bt = i / C;
    int t  = bt % TSEQ;
    x[i] = wte[(size_t)idx[bt] * C + c] + wpe[(size_t)t * C + c];
}

// ---------------- layernorm -> split bf16 ----------------
__global__ void ln_kernel(const float* __restrict__ in,
                          const float* __restrict__ w,
                          const float* __restrict__ b,
                          __nv_bfloat16* __restrict__ out_h,
                          __nv_bfloat16* __restrict__ out_l) {
    int row = blockIdx.x;
    int tid = threadIdx.x;                 // 256 threads
    const float* p = in + (size_t)row * C;

    float v[3];
    float s1 = 0.f, s2 = 0.f;
#pragma unroll
    for (int i = 0; i < 3; ++i) {
        v[i] = p[tid + i * 256];
        s1 += v[i];
        s2 += v[i] * v[i];
    }
#pragma unroll
    for (int o = 16; o > 0; o >>= 1) {
        s1 += __shfl_xor_sync(0xFFFFFFFFu, s1, o);
        s2 += __shfl_xor_sync(0xFFFFFFFFu, s2, o);
    }
    __shared__ float r1[8], r2[8];
    __shared__ float s_mu, s_rstd;
    int lane = tid & 31, warp = tid >> 5;
    if (lane == 0) { r1[warp] = s1; r2[warp] = s2; }
    __syncthreads();
    if (tid == 0) {
        float a = 0.f, q = 0.f;
#pragma unroll
        for (int i = 0; i < 8; ++i) { a += r1[i]; q += r2[i]; }
        float mu  = a / (float)C;
        float var = q / (float)C - mu * mu;
        s_mu   = mu;
        s_rstd = rsqrtf(var + 1e-5f);
    }
    __syncthreads();
    float mu = s_mu, rstd = s_rstd;
#pragma unroll
    for (int i = 0; i < 3; ++i) {
        int c = tid + i * 256;
        float o = (v[i] - mu) * rstd * w[c] + b[c];
        __nv_bfloat16 h, lo;
        split_bf16(o, &h, &lo);
        out_h[(size_t)row * C + c] = h;
        out_l[(size_t)row * C + c] = lo;
    }
}

// ---------------- mma.sync GEMM ----------------
// D[M=2048, N] = (Ah+Al)[M,K] @ (Bh+Bl)^T  where B is [N,K] row-major (transposed W).
// 3-term split: ah*bh + ah*bl + al*bh, fp32 accumulation.
// epi: 0 = bias+store fp32, 1 = bias+GELU -> split bf16, 2 = bias+residual -> fp32
// CTA tile 128x128, BK=32, 8 warps in 2(M)x4(N); warp tile 64x32.
#define PAD 40   // smem row stride in bf16 (80B): conflict-free ldmatrix

__global__ __launch_bounds__(256)
void mma_gemm_kernel(const __nv_bfloat16* __restrict__ Ah, const __nv_bfloat16* __restrict__ Al,
                     const __nv_bfloat16* __restrict__ Bh, const __nv_bfloat16* __restrict__ Bl,
                     const float* __restrict__ bias, const float* __restrict__ res,
                     float* __restrict__ outf,
                     __nv_bfloat16* __restrict__ oh, __nv_bfloat16* __restrict__ ol,
                     int N, int K, int epi)
{
    __shared__ __nv_bfloat16 sAh[128 * PAD], sAl[128 * PAD];
    __shared__ __nv_bfloat16 sBh[128 * PAD], sBl[128 * PAD];

    int tid = threadIdx.x, wid = tid >> 5, lane = tid & 31;
    int n0 = blockIdx.x * 128, m0 = blockIdx.y * 128;
    int wm = (wid & 1) * 64;     // warp M offset
    int wn = (wid >> 1) * 32;    // warp N offset

    float acc[4][4][4];
#pragma unroll
    for (int i = 0; i < 4; ++i)
#pragma unroll
        for (int j = 0; j < 4; ++j)
#pragma unroll
            for (int r = 0; r < 4; ++r) acc[i][j][r] = 0.f;

    // ldmatrix source addresses (fixed per thread, advance by ks)
    uint32_t aAh = smem_u32(&sAh[(wm + (lane & 15)) * PAD + ((lane >> 4) << 3)]);
    uint32_t aAl = smem_u32(&sAl[(wm + (lane & 15)) * PAD + ((lane >> 4) << 3)]);
    uint32_t aBh = smem_u32(&sBh[(wn + (lane & 7)) * PAD + (((lane >> 3) & 1) << 3)]);
    uint32_t aBl = smem_u32(&sBl[(wn + (lane & 7)) * PAD + (((lane >> 3) & 1) << 3)]);

    int ldrow = tid >> 2;            // 0..63 (x2 iters -> 128 rows)
    int ldc8  = (tid & 3) << 3;      // bf16 col offset 0,8,16,24

    for (int k0 = 0; k0 < K; k0 += 32) {
#pragma unroll
        for (int i = 0; i < 2; ++i) {
            int row = ldrow + i * 64;
            size_t ga = (size_t)(m0 + row) * K + k0 + ldc8;
            size_t gb = (size_t)(n0 + row) * K + k0 + ldc8;
            int so = row * PAD + ldc8;
            *(uint4*)&sAh[so] = *(const uint4*)(Ah + ga);
            *(uint4*)&sAl[so] = *(const uint4*)(Al + ga);
            *(uint4*)&sBh[so] = *(const uint4*)(Bh + gb);
            *(uint4*)&sBl[so] = *(const uint4*)(Bl + gb);
        }
        __syncthreads();

#pragma unroll
        for (int ks = 0; ks < 2; ++ks) {
            uint32_t koff = ks * 16 * 2;   // byte offset for k half
            uint32_t bh[4][2], bl[4][2];
#pragma unroll
            for (int ni = 0; ni < 4; ++ni) {
                ldsm_x2(bh[ni], aBh + ni * 8 * PAD * 2 + koff);
                ldsm_x2(bl[ni], aBl + ni * 8 * PAD * 2 + koff);
            }
#pragma unroll
            for (int mi = 0; mi < 4; ++mi) {
                uint32_t ah[4], al[4];
                ldsm_x4(ah, aAh + mi * 16 * PAD * 2 + koff);
                ldsm_x4(al, aAl + mi * 16 * PAD * 2 + koff);
#pragma unroll
                for (int ni = 0; ni < 4; ++ni) {
                    mma_bf16(acc[mi][ni], ah, bh[ni]);
                    mma_bf16(acc[mi][ni], ah, bl[ni]);
                    mma_bf16(acc[mi][ni], al, bh[ni]);
                }
            }
        }
        __syncthreads();
    }

    // epilogue: acc frag c0:(r,c) c1:(r,c+1) c2:(r+8,c) c3:(r+8,c+1); r=lane/4, c=2*(lane%4)
#pragma unroll
    for (int mi = 0; mi < 4; ++mi) {
#pragma unroll
        for (int ni = 0; ni < 4; ++ni) {
            int m = m0 + wm + mi * 16 + (lane >> 2);
            int n = n0 + wn + ni * 8 + ((lane & 3) << 1);
#pragma unroll
            for (int half = 0; half < 2; ++half) {
                int mm = m + half * 8;
#pragma unroll
                for (int s = 0; s < 2; ++s) {
                    int nn = n + s;
                    if (nn < N) {
                        float v = acc[mi][ni][half * 2 + s] + (bias ? bias[nn] : 0.f);
                        size_t o = (size_t)mm * N + nn;
                        if (epi == 0) {
                            outf[o] = v;
                        } else if (epi == 1) {
                            v = 0.5f * v * (1.f + tanhf(0.7978845608028654f * (v + 0.044715f * v * v * v)));
                            __nv_bfloat16 h, lo;
                            split_bf16(v, &h, &lo);
                            oh[o] = h; ol[o] = lo;
                        } else {
                            outf[o] = v + res[o];
                        }
                    }
                }
            }
        }
    }
}

// ---------------- causal attention: thread per query, smem K/V tiles ----------------
#define QT 128     // queries per block (== threads per block)
#define KT 16      // keys per smem tile

__global__ __launch_bounds__(QT) void attn_kernel(const float* __restrict__ qkv,
                                                  __nv_bfloat16* __restrict__ out_h,
                                                  __nv_bfloat16* __restrict__ out_l) {
    __shared__ float Ks[KT][HD];
    __shared__ float Vs[KT][HD];

    int tid = threadIdx.x;
    int qt  = gridDim.x - 1 - blockIdx.x;   // heaviest q-tiles first
    int q   = qt * QT + tid;
    int bh  = blockIdx.y;
    int b   = bh / NH, h = bh % NH;

    const float* base = qkv + (size_t)b * TSEQ * C3 + h * HD;

    ull q2[HD / 2];
    {
        const ulonglong2* qp = (const ulonglong2*)(base + (size_t)q * C3);
        ull scale = pack2(0.125f, 0.125f);
#pragma unroll
        for (int i = 0; i < HD / 4; ++i) {
            ulonglong2 v = qp[i];
            q2[2 * i + 0] = mul2(v.x, scale);
            q2[2 * i + 1] = mul2(v.y, scale);
        }
    }

    ull acc2[HD / 2];
#pragma unroll
    for (int i = 0; i < HD / 2; ++i) acc2[i] = 0ULL;
    float m = -3e38f, l = 0.f;

    int ntiles = (qt * QT + QT - 1) / KT + 1;
    for (int t = 0; t < ntiles; ++t) {
        int k0 = t * KT;
        __syncthreads();
#pragma unroll
        for (int i = 0; i < (KT * HD / 4) / QT; ++i) {
            int idx = tid + i * QT;
            int k  = idx >> 4;
            int d4 = (idx & 15) * 4;
            const float* row = base + (size_t)(k0 + k) * C3;
            *(float4*)&Ks[k][d4] = *(const float4*)(row + C + d4);
            *(float4*)&Vs[k][d4] = *(const float4*)(row + 2 * C + d4);
        }
        __syncthreads();

        float s[KT];
#pragma unroll
        for (int k = 0; k < KT; ++k) {
            const ulonglong2* kp = (const ulonglong2*)&Ks[k][0];
            ull sa = 0ULL, sb2 = 0ULL;
#pragma unroll
            for (int d = 0; d < HD / 4; ++d) {
                ulonglong2 kv = kp[d];
                sa  = fma2(q2[2 * d + 0], kv.x, sa);
                sb2 = fma2(q2[2 * d + 1], kv.y, sb2);
            }
            float2 ua = unpack2(sa);
            float2 ub = unpack2(sb2);
            s[k] = (ua.x + ua.y) + (ub.x + ub.y);
        }

        float mt = -3e38f;
#pragma unroll
        for (int k = 0; k < KT; ++k)
            if (k0 + k <= q) mt = fmaxf(mt, s[k]);
        float mn = fmaxf(m, mt);
        float alpha = __expf(m - mn);
        ull al2 = pack2(alpha, alpha);
#pragma unroll
        for (int d = 0; d < HD / 2; ++d) acc2[d] = mul2(acc2[d], al2);
        l *= alpha;
#pragma unroll
        for (int k = 0; k < KT; ++k) {
            float p = (k0 + k <= q) ? __expf(s[k] - mn) : 0.f;
            l += p;
            ull p2 = pack2(p, p);
            const ulonglong2* vp = (const ulonglong2*)&Vs[k][0];
#pragma unroll
            for (int d = 0; d < HD / 4; ++d) {
                ulonglong2 vv = vp[d];
                acc2[2 * d + 0] = fma2(p2, vv.x, acc2[2 * d + 0]);
                acc2[2 * d + 1] = fma2(p2, vv.y, acc2[2 * d + 1]);
            }
        }
        m = mn;
    }

    float inv = 1.f / l;
    size_t ob = (size_t)(b * TSEQ + q) * C + h * HD;
#pragma unroll
    for (int d = 0; d < HD / 2; ++d) {
        float2 u = unpack2(acc2[d]);
        __nv_bfloat16 h0, l0, h1, l1;
        split_bf16(u.x * inv, &h0, &l0);
        split_bf16(u.y * inv, &h1, &l1);
        out_h[ob + 2 * d + 0] = h0;  out_l[ob + 2 * d + 0] = l0;
        out_h[ob + 2 * d + 1] = h1;  out_l[ob + 2 * d + 1] = l1;
    }
}

// ---------------- launch ----------------
extern "C" void kernel_launch(void* const* d_in, const int* in_sizes, int n_in,
                              void* d_out, int out_size) {
    const int*   idx      = (const int*)  d_in[0];
    const float* wte      = (const float*)d_in[1];
    const float* wpe      = (const float*)d_in[2];
    const float* ln1_w    = (const float*)d_in[3];
    const float* ln1_b    = (const float*)d_in[4];
    const float* attn_w   = (const float*)d_in[5];
    const float* attn_b   = (const float*)d_in[6];
    const float* proj_w   = (const float*)d_in[7];
    const float* proj_b   = (const float*)d_in[8];
    const float* ln2_w    = (const float*)d_in[9];
    const float* ln2_b    = (const float*)d_in[10];
    const float* fc_w     = (const float*)d_in[11];
    const float* fc_b     = (const float*)d_in[12];
    const float* fcproj_w = (const float*)d_in[13];
    const float* fcproj_b = (const float*)d_in[14];
    const float* lnf_w    = (const float*)d_in[15];
    const float* lnf_b    = (const float*)d_in[16];
    const float* lm_head  = (const float*)d_in[17];
    float* out = (float*)d_out;

    float *x, *qkv;
    __nv_bfloat16 *lnh, *lnl, *atth, *attl, *hh, *hl;
    __nv_bfloat16 *wqh, *wql, *wph, *wpl, *wfh, *wfl, *wgh, *wgl, *wlh, *wll;
    cudaGetSymbolAddress((void**)&x,    g_x);
    cudaGetSymbolAddress((void**)&qkv,  g_qkv);
    cudaGetSymbolAddress((void**)&lnh,  g_ln_h);
    cudaGetSymbolAddress((void**)&lnl,  g_ln_l);
    cudaGetSymbolAddress((void**)&atth, g_att_h);
    cudaGetSymbolAddress((void**)&attl, g_att_l);
    cudaGetSymbolAddress((void**)&hh,   g_h_h);
    cudaGetSymbolAddress((void**)&hl,   g_h_l);
    cudaGetSymbolAddress((void**)&wqh,  g_wqkv_h);
    cudaGetSymbolAddress((void**)&wql,  g_wqkv_l);
    cudaGetSymbolAddress((void**)&wph,  g_wproj_h);
    cudaGetSymbolAddress((void**)&wpl,  g_wproj_l);
    cudaGetSymbolAddress((void**)&wfh,  g_wfc_h);
    cudaGetSymbolAddress((void**)&wfl,  g_wfc_l);
    cudaGetSymbolAddress((void**)&wgh,  g_wfcp_h);
    cudaGetSymbolAddress((void**)&wgl,  g_wfcp_l);
    cudaGetSymbolAddress((void**)&wlh,  g_wlm_h);
    cudaGetSymbolAddress((void**)&wll,  g_wlm_l);

    dim3 cb(32, 8);
    // weight convert + transpose (every call; deterministic)
    convw_kernel<<<dim3(C3 / 32,  C / 32,  LAYERS), cb>>>(attn_w,   wqh, wql, C,  C3,    C3);
    convw_kernel<<<dim3(C / 32,   C / 32,  LAYERS), cb>>>(proj_w,   wph, wpl, C,  C,     C);
    convw_kernel<<<dim3(C4 / 32,  C / 32,  LAYERS), cb>>>(fc_w,     wfh, wfl, C,  C4,    C4);
    convw_kernel<<<dim3(C / 32,   C4 / 32, LAYERS), cb>>>(fcproj_w, wgh, wgl, C4, C,     C);
    convw_kernel<<<dim3(VPAD / 32, C / 32, 1),      cb>>>(lm_head,  wlh, wll, C,  VOCAB, VPAD);

    embed_kernel<<<(NTOK * C + 255) / 256, 256>>>(idx, wte, wpe, x);

    const int MT = NTOK / 128;   // 16 M-tiles
    for (int l = 0; l < LAYERS; ++l) {
        ln_kernel<<<NTOK, 256>>>(x, ln1_w + l * C, ln1_b + l * C, lnh, lnl);
        mma_gemm_kernel<<<dim3(C3 / 128, MT), 256>>>(
            lnh, lnl, wqh + (size_t)l * C3 * C, wql + (size_t)l * C3 * C,
            attn_b + (size_t)l * C3, nullptr, qkv, nullptr, nullptr, C3, C, 0);
        attn_kernel<<<dim3(TSEQ / QT, BATCH * NH), QT>>>(qkv, atth, attl);
        mma_gemm_kernel<<<dim3(C / 128, MT), 256>>>(
            atth, attl, wph + (size_t)l * C * C, wpl + (size_t)l * C * C,
            proj_b + (size_t)l * C, x, x, nullptr, nullptr, C, C, 2);
        ln_kernel<<<NTOK, 256>>>(x, ln2_w + l * C, ln2_b + l * C, lnh, lnl);
        mma_gemm_kernel<<<dim3(C4 / 128, MT), 256>>>(
            lnh, lnl, wfh + (size_t)l * C4 * C, wfl + (size_t)l * C4 * C,
            fc_b + (size_t)l * C4, nullptr, nullptr, hh, hl, C4, C, 1);
        mma_gemm_kernel<<<dim3(C / 128, MT), 256>>>(
            hh, hl, wgh + (size_t)l * C * C4, wgl + (size_t)l * C * C4,
            fcproj_b + (size_t)l * C, x, x, nullptr, nullptr, C, C4, 2);
    }

    ln_kernel<<<NTOK, 256>>>(x, lnf_w, lnf_b, lnh, lnl);
    mma_gemm_kernel<<<dim3(VPAD / 128, MT), 256>>>(
        lnh, lnl, wlh, wll, nullptr, nullptr, out, nullptr, nullptr, VOCAB, C, 0);
}

// round 9
// speedup vs baseline: 2.0069x; 1.0683x over previous
#include <cuda_runtime.h>
#include <cuda_bf16.h>
#include <math.h>
#include <stdint.h>

// ---------------- GPT-2 small config ----------------
#define LAYERS 12
#define NH     12
#define C      768
#define HD     64
#define TSEQ   1024
#define BATCH  2
#define NTOK   (BATCH * TSEQ)      // 2048
#define VOCAB  50257
#define VPAD   50304               // VOCAB padded to 128
#define C3     (3 * C)             // 2304
#define C4     (4 * C)             // 3072

typedef unsigned long long ull;

// ---------------- packed fp32x2 helpers ----------------
__device__ __forceinline__ ull fma2(ull a, ull b, ull c) {
    ull d; asm("fma.rn.f32x2 %0, %1, %2, %3;" : "=l"(d) : "l"(a), "l"(b), "l"(c)); return d;
}
__device__ __forceinline__ ull mul2(ull a, ull b) {
    ull d; asm("mul.rn.f32x2 %0, %1, %2;" : "=l"(d) : "l"(a), "l"(b)); return d;
}
__device__ __forceinline__ ull pack2(float lo, float hi) {
    ull d; asm("mov.b64 %0, {%1, %2};" : "=l"(d) : "r"(__float_as_uint(lo)), "r"(__float_as_uint(hi))); return d;
}
__device__ __forceinline__ float2 unpack2(ull v) {
    unsigned lo, hi; asm("mov.b64 {%0, %1}, %2;" : "=r"(lo), "=r"(hi) : "l"(v));
    return make_float2(__uint_as_float(lo), __uint_as_float(hi));
}

__device__ __forceinline__ uint32_t smem_u32(const void* p) {
    uint32_t a;
    asm("{ .reg .u64 t; cvta.to.shared.u64 t, %1; cvt.u32.u64 %0, t; }" : "=r"(a) : "l"(p));
    return a;
}

__device__ __forceinline__ void split_bf16(float v, __nv_bfloat16* h, __nv_bfloat16* l) {
    __nv_bfloat16 hi = __float2bfloat16(v);
    *h = hi;
    *l = __float2bfloat16(v - __bfloat162float(hi));
}

// ---------------- mma.sync + cp.async helpers (sm_80 baseline) ----------------
__device__ __forceinline__ void ldsm_x4(uint32_t* r, uint32_t addr) {
    asm volatile("ldmatrix.sync.aligned.m8n8.x4.shared.b16 {%0,%1,%2,%3}, [%4];"
                 : "=r"(r[0]), "=r"(r[1]), "=r"(r[2]), "=r"(r[3]) : "r"(addr));
}
__device__ __forceinline__ void ldsm_x2(uint32_t* r, uint32_t addr) {
    asm volatile("ldmatrix.sync.aligned.m8n8.x2.shared.b16 {%0,%1}, [%2];"
                 : "=r"(r[0]), "=r"(r[1]) : "r"(addr));
}
__device__ __forceinline__ void mma_bf16(float* c, const uint32_t* a, const uint32_t* b) {
    asm volatile(
        "mma.sync.aligned.m16n8k16.row.col.f32.bf16.bf16.f32 "
        "{%0,%1,%2,%3}, {%4,%5,%6,%7}, {%8,%9}, {%0,%1,%2,%3};"
        : "+f"(c[0]), "+f"(c[1]), "+f"(c[2]), "+f"(c[3])
        : "r"(a[0]), "r"(a[1]), "r"(a[2]), "r"(a[3]), "r"(b[0]), "r"(b[1]));
}
__device__ __forceinline__ void cp16(uint32_t dst, const void* src) {
    asm volatile("cp.async.cg.shared.global [%0], [%1], 16;" :: "r"(dst), "l"(src));
}
__device__ __forceinline__ void cp_commit() {
    asm volatile("cp.async.commit_group;" ::: "memory");
}

// ---------------- scratch (static __device__, no allocation) ----------------
__device__ float g_x  [NTOK * C];            // residual stream (fp32)
__device__ float g_qkv[NTOK * C3];           // qkv projection (fp32)
__device__ __nv_bfloat16 g_ln_h [NTOK * C],  g_ln_l [NTOK * C];
__device__ __nv_bfloat16 g_att_h[NTOK * C],  g_att_l[NTOK * C];
__device__ __nv_bfloat16 g_h_h  [NTOK * C4], g_h_l  [NTOK * C4];
// transposed split-bf16 weights: [N, K] row-major
__device__ __nv_bfloat16 g_wqkv_h[LAYERS * C3 * C],  g_wqkv_l[LAYERS * C3 * C];
__device__ __nv_bfloat16 g_wproj_h[LAYERS * C * C],  g_wproj_l[LAYERS * C * C];
__device__ __nv_bfloat16 g_wfc_h [LAYERS * C4 * C],  g_wfc_l [LAYERS * C4 * C];
__device__ __nv_bfloat16 g_wfcp_h[LAYERS * C * C4],  g_wfcp_l[LAYERS * C * C4];
__device__ __nv_bfloat16 g_wlm_h [VPAD * C],         g_wlm_l [VPAD * C];

// ---------------- weight convert + transpose: W[L,K,N] -> Wt[L,Npad,K] split bf16 ----------------
__global__ void convw_kernel(const float* __restrict__ W,
                             __nv_bfloat16* __restrict__ Th,
                             __nv_bfloat16* __restrict__ Tl,
                             int K, int N, int Npad) {
    __shared__ float t[32][33];
    int l = blockIdx.z;
    int n0 = blockIdx.x * 32, k0 = blockIdx.y * 32;
    int tx = threadIdx.x, ty = threadIdx.y;    // 32 x 8
    const float* Wl = W + (size_t)l * K * N;
#pragma unroll
    for (int i = 0; i < 4; ++i) {
        int k = k0 + ty + i * 8;
        int n = n0 + tx;
        t[ty + i * 8][tx] = (n < N) ? Wl[(size_t)k * N + n] : 0.f;
    }
    __syncthreads();
    size_t obase = (size_t)l * Npad * K;
#pragma unroll
    for (int i = 0; i < 4; ++i) {
        int nl = ty + i * 8;
        float v = t[tx][nl];
        __nv_bfloat16 h, lo;
        split_bf16(v, &h, &lo);
        size_t o = obase + (size_t)(n0 + nl) * K + k0 + tx;
        Th[o] = h;
        Tl[o] = lo;
    }
}

// ---------------- embedding ----------------
__global__ void embed_kernel(const int* __restrict__ idx,
                             const float* __restrict__ wte,
                             const float* __restrict__ wpe,
                             float* __restrict__ x) {
    int i = blockIdx.x * blockDim.x + threadIdx.x;
    if (i >= NTOK * C) return;
    int c  = i % C;
    int bt = i / C;
    int t  = bt % TSEQ;
    x[i] = wte[(size_t)idx[bt] * C + c] + wpe[(size_t)t * C + c];
}

// ---------------- layernorm -> split bf16 ----------------
__global__ void ln_kernel(const float* __restrict__ in,
                          const float* __restrict__ w,
                          const float* __restrict__ b,
                          __nv_bfloat16* __restrict__ out_h,
                          __nv_bfloat16* __restrict__ out_l) {
    int row = blockIdx.x;
    int tid = threadIdx.x;                 // 256 threads
    const float* p = in + (size_t)row * C;

    float v[3];
    float s1 = 0.f, s2 = 0.f;
#pragma unroll
    for (int i = 0; i < 3; ++i) {
        v[i] = p[tid + i * 256];
        s1 += v[i];
        s2 += v[i] * v[i];
    }
#pragma unroll
    for (int o = 16; o > 0; o >>= 1) {
        s1 += __shfl_xor_sync(0xFFFFFFFFu, s1, o);
        s2 += __shfl_xor_sync(0xFFFFFFFFu, s2, o);
    }
    __shared__ float r1[8], r2[8];
    __shared__ float s_mu, s_rstd;
    int lane = tid & 31, warp = tid >> 5;
    if (lane == 0) { r1[warp] = s1; r2[warp] = s2; }
    __syncthreads();
    if (tid == 0) {
        float a = 0.f, q = 0.f;
#pragma unroll
        for (int i = 0; i < 8; ++i) { a += r1[i]; q += r2[i]; }
        float mu  = a / (float)C;
        float var = q / (float)C - mu * mu;
        s_mu   = mu;
        s_rstd = rsqrtf(var + 1e-5f);
    }
    __syncthreads();
    float mu = s_mu, rstd = s_rstd;
#pragma unroll
    for (int i = 0; i < 3; ++i) {
        int c = tid + i * 256;
        float o = (v[i] - mu) * rstd * w[c] + b[c];
        __nv_bfloat16 h, lo;
        split_bf16(o, &h, &lo);
        out_h[(size_t)row * C + c] = h;
        out_l[(size_t)row * C + c] = lo;
    }
}

// ---------------- mma.sync GEMM, 2-stage cp.async pipeline ----------------
// D[M=2048, N] = (Ah+Al)[M,K] @ (Bh+Bl)^T  (B is [N,K] row-major, transposed W).
// 3-term split: ah*bh + ah*bl + al*bh, fp32 accumulation.
// epi: 0 = bias+store fp32, 1 = bias+GELU -> split bf16, 2 = bias+residual -> fp32
// CTA tile 128x128, BK=32, 8 warps in 2(M)x4(N); warp tile 64x32.
#define PAD 40                         // smem row stride in bf16 (80B)
#define ARR_B   (128 * PAD * 2)        // bytes per tile array (10240)
#define STAGE_B (4 * ARR_B)            // bytes per stage (40960)
#define SMEM_DYN (2 * STAGE_B)         // 81920

__global__ __launch_bounds__(256)
void mma_gemm_kernel(const __nv_bfloat16* __restrict__ Ah, const __nv_bfloat16* __restrict__ Al,
                     const __nv_bfloat16* __restrict__ Bh, const __nv_bfloat16* __restrict__ Bl,
                     const float* __restrict__ bias, const float* __restrict__ res,
                     float* __restrict__ outf,
                     __nv_bfloat16* __restrict__ oh, __nv_bfloat16* __restrict__ ol,
                     int N, int K, int epi)
{
    extern __shared__ char dsm[];
    uint32_t sb = smem_u32(dsm);

    int tid = threadIdx.x, wid = tid >> 5, lane = tid & 31;
    int n0 = blockIdx.x * 128, m0 = blockIdx.y * 128;
    int wm = (wid & 1) * 64;     // warp M offset
    int wn = (wid >> 1) * 32;    // warp N offset

    float acc[4][4][4];
#pragma unroll
    for (int i = 0; i < 4; ++i)
#pragma unroll
        for (int j = 0; j < 4; ++j)
#pragma unroll
            for (int r = 0; r < 4; ++r) acc[i][j][r] = 0.f;

    // ldmatrix source byte offsets within a stage
    uint32_t oAh = ((wm + (lane & 15)) * PAD + ((lane >> 4) << 3)) * 2;
    uint32_t oB  = ((wn + (lane & 7)) * PAD + (((lane >> 3) & 1) << 3)) * 2;

    int ldrow = tid >> 2;            // 0..63 (x2 iters -> 128 rows)
    int ldc8  = (tid & 3) << 3;      // bf16 col offset 0,8,16,24

    int nch = K >> 5;

    // issue cp.async loads of chunk c into stage s
    auto load_chunk = [&](int c, int s) {
        int k0 = c << 5;
        uint32_t stb = sb + s * STAGE_B;
#pragma unroll
        for (int i = 0; i < 2; ++i) {
            int row = ldrow + i * 64;
            size_t ga = (size_t)(m0 + row) * K + k0 + ldc8;
            size_t gb = (size_t)(n0 + row) * K + k0 + ldc8;
            uint32_t so = (uint32_t)(row * PAD + ldc8) * 2;
            cp16(stb + 0 * ARR_B + so, Ah + ga);
            cp16(stb + 1 * ARR_B + so, Al + ga);
            cp16(stb + 2 * ARR_B + so, Bh + gb);
            cp16(stb + 3 * ARR_B + so, Bl + gb);
        }
    };

    load_chunk(0, 0);
    cp_commit();

    for (int c = 0; c < nch; ++c) {
        if (c + 1 < nch) { load_chunk(c + 1, (c + 1) & 1); cp_commit(); }
        if (c + 1 < nch) asm volatile("cp.async.wait_group 1;" ::: "memory");
        else             asm volatile("cp.async.wait_group 0;" ::: "memory");
        __syncthreads();

        uint32_t stb = sb + (c & 1) * STAGE_B;
        uint32_t aAh = stb + 0 * ARR_B + oAh;
        uint32_t aAl = stb + 1 * ARR_B + oAh;
        uint32_t aBh = stb + 2 * ARR_B + oB;
        uint32_t aBl = stb + 3 * ARR_B + oB;

#pragma unroll
        for (int ks = 0; ks < 2; ++ks) {
            uint32_t koff = ks * 16 * 2;   // byte offset for k half
            uint32_t bh[4][2], bl[4][2];
#pragma unroll
            for (int ni = 0; ni < 4; ++ni) {
                ldsm_x2(bh[ni], aBh + ni * 8 * PAD * 2 + koff);
                ldsm_x2(bl[ni], aBl + ni * 8 * PAD * 2 + koff);
            }
#pragma unroll
            for (int mi = 0; mi < 4; ++mi) {
                uint32_t ah[4], al[4];
                ldsm_x4(ah, aAh + mi * 16 * PAD * 2 + koff);
                ldsm_x4(al, aAl + mi * 16 * PAD * 2 + koff);
#pragma unroll
                for (int ni = 0; ni < 4; ++ni) {
                    mma_bf16(acc[mi][ni], ah, bh[ni]);
                    mma_bf16(acc[mi][ni], ah, bl[ni]);
                    mma_bf16(acc[mi][ni], al, bh[ni]);
                }
            }
        }
        __syncthreads();
    }

    // epilogue: acc frag c0:(r,c) c1:(r,c+1) c2:(r+8,c) c3:(r+8,c+1); r=lane/4, c=2*(lane%4)
#pragma unroll
    for (int mi = 0; mi < 4; ++mi) {
#pragma unroll
        for (int ni = 0; ni < 4; ++ni) {
            int m = m0 + wm + mi * 16 + (lane >> 2);
            int n = n0 + wn + ni * 8 + ((lane & 3) << 1);
#pragma unroll
            for (int half = 0; half < 2; ++half) {
                int mm = m + half * 8;
#pragma unroll
                for (int s = 0; s < 2; ++s) {
                    int nn = n + s;
                    if (nn < N) {
                        float v = acc[mi][ni][half * 2 + s] + (bias ? bias[nn] : 0.f);
                        size_t o = (size_t)mm * N + nn;
                        if (epi == 0) {
                            outf[o] = v;
                        } else if (epi == 1) {
                            v = 0.5f * v * (1.f + tanhf(0.7978845608028654f * (v + 0.044715f * v * v * v)));
                            __nv_bfloat16 h, lo;
                            split_bf16(v, &h, &lo);
                            oh[o] = h; ol[o] = lo;
                        } else {
                            outf[o] = v + res[o];
                        }
                    }
                }
            }
        }
    }
}

// ---------------- causal attention: 4 threads per query, smem K/V tiles ----------------
#define QPB 32     // queries per block (128 threads / 4)
#define KT  16     // keys per smem tile

__global__ __launch_bounds__(128) void attn_kernel(const float* __restrict__ qkv,
                                                   __nv_bfloat16* __restrict__ out_h,
                                                   __nv_bfloat16* __restrict__ out_l) {
    __shared__ float Ks[KT][HD];
    __shared__ float Vs[KT][HD];

    int tid = threadIdx.x;
    int g   = tid & 3;                      // dim-slice 0..3 (16 dims each)
    int qi  = tid >> 2;                     // query within block 0..31
    int qt  = gridDim.x - 1 - blockIdx.x;   // heaviest q-tiles first
    int q   = qt * QPB + qi;
    int bh  = blockIdx.y;
    int b   = bh / NH, h = bh % NH;
    int d0  = g * 16;                       // first dim this thread owns

    const float* base = qkv + (size_t)b * TSEQ * C3 + h * HD;

    // load this thread's 16 query dims (scaled by 1/sqrt(HD))
    ull q2[8];
    {
        const ulonglong2* qp = (const ulonglong2*)(base + (size_t)q * C3 + d0);
        ull scale = pack2(0.125f, 0.125f);
#pragma unroll
        for (int i = 0; i < 4; ++i) {
            ulonglong2 v = qp[i];
            q2[2 * i + 0] = mul2(v.x, scale);
            q2[2 * i + 1] = mul2(v.y, scale);
        }
    }

    ull acc2[8];
#pragma unroll
    for (int i = 0; i < 8; ++i) acc2[i] = 0ULL;
    float m = -3e38f, l = 0.f;

    int ntiles = (qt * QPB + QPB - 1) / KT + 1;
    for (int t = 0; t < ntiles; ++t) {
        int k0 = t * KT;
        __syncthreads();
        // cooperative K/V tile load: KT*HD/4 = 256 float4 each, 128 threads -> 2 iters
#pragma unroll
        for (int i = 0; i < 2; ++i) {
            int idx = tid + i * 128;
            int k  = idx >> 4;
            int d4 = (idx & 15) * 4;
            const float* row = base + (size_t)(k0 + k) * C3;
            *(float4*)&Ks[k][d4] = *(const float4*)(row + C + d4);
            *(float4*)&Vs[k][d4] = *(const float4*)(row + 2 * C + d4);
        }
        __syncthreads();

        // scores: partial dot over 16 dims, reduce across quad
        float s[KT];
#pragma unroll
        for (int k = 0; k < KT; ++k) {
            const ulonglong2* kp = (const ulonglong2*)&Ks[k][d0];
            ull sa = 0ULL, sb2 = 0ULL;
#pragma unroll
            for (int d = 0; d < 4; ++d) {
                ulonglong2 kv = kp[d];
                sa  = fma2(q2[2 * d + 0], kv.x, sa);
                sb2 = fma2(q2[2 * d + 1], kv.y, sb2);
            }
            float2 ua = unpack2(sa);
            float2 ub = unpack2(sb2);
            float sp = (ua.x + ua.y) + (ub.x + ub.y);
            sp += __shfl_xor_sync(0xFFFFFFFFu, sp, 1);
            sp += __shfl_xor_sync(0xFFFFFFFFu, sp, 2);
            s[k] = sp;
        }

        // online softmax update (state duplicated across the quad; deterministic)
        float mt = -3e38f;
#pragma unroll
        for (int k = 0; k < KT; ++k)
            if (k0 + k <= q) mt = fmaxf(mt, s[k]);
        float mn = fmaxf(m, mt);
        float alpha = __expf(m - mn);
        ull al2 = pack2(alpha, alpha);
#pragma unroll
        for (int d = 0; d < 8; ++d) acc2[d] = mul2(acc2[d], al2);
        l *= alpha;
#pragma unroll
        for (int k = 0; k < KT; ++k) {
            float p = (k0 + k <= q) ? __expf(s[k] - mn) : 0.f;
            l += p;
            ull p2 = pack2(p, p);
            const ulonglong2* vp = (const ulonglong2*)&Vs[k][d0];
#pragma unroll
            for (int d = 0; d < 4; ++d) {
                ulonglong2 vv = vp[d];
                acc2[2 * d + 0] = fma2(p2, vv.x, acc2[2 * d + 0]);
                acc2[2 * d + 1] = fma2(p2, vv.y, acc2[2 * d + 1]);
            }
        }
        m = mn;
    }

    float inv = 1.f / l;
    size_t ob = (size_t)(b * TSEQ + q) * C + h * HD + d0;
#pragma unroll
    for (int d = 0; d < 8; ++d) {
        float2 u = unpack2(acc2[d]);
        __nv_bfloat16 h0, l0, h1, l1;
        split_bf16(u.x * inv, &h0, &l0);
        split_bf16(u.y * inv, &h1, &l1);
        out_h[ob + 2 * d + 0] = h0;  out_l[ob + 2 * d + 0] = l0;
        out_h[ob + 2 * d + 1] = h1;  out_l[ob + 2 * d + 1] = l1;
    }
}

// ---------------- launch ----------------
extern "C" void kernel_launch(void* const* d_in, const int* in_sizes, int n_in,
                              void* d_out, int out_size) {
    const int*   idx      = (const int*)  d_in[0];
    const float* wte      = (const float*)d_in[1];
    const float* wpe      = (const float*)d_in[2];
    const float* ln1_w    = (const float*)d_in[3];
    const float* ln1_b    = (const float*)d_in[4];
    const float* attn_w   = (const float*)d_in[5];
    const float* attn_b   = (const float*)d_in[6];
    const float* proj_w   = (const float*)d_in[7];
    const float* proj_b   = (const float*)d_in[8];
    const float* ln2_w    = (const float*)d_in[9];
    const float* ln2_b    = (const float*)d_in[10];
    const float* fc_w     = (const float*)d_in[11];
    const float* fc_b     = (const float*)d_in[12];
    const float* fcproj_w = (const float*)d_in[13];
    const float* fcproj_b = (const float*)d_in[14];
    const float* lnf_w    = (const float*)d_in[15];
    const float* lnf_b    = (const float*)d_in[16];
    const float* lm_head  = (const float*)d_in[17];
    float* out = (float*)d_out;

    float *x, *qkv;
    __nv_bfloat16 *lnh, *lnl, *atth, *attl, *hh, *hl;
    __nv_bfloat16 *wqh, *wql, *wph, *wpl, *wfh, *wfl, *wgh, *wgl, *wlh, *wll;
    cudaGetSymbolAddress((void**)&x,    g_x);
    cudaGetSymbolAddress((void**)&qkv,  g_qkv);
    cudaGetSymbolAddress((void**)&lnh,  g_ln_h);
    cudaGetSymbolAddress((void**)&lnl,  g_ln_l);
    cudaGetSymbolAddress((void**)&atth, g_att_h);
    cudaGetSymbolAddress((void**)&attl, g_att_l);
    cudaGetSymbolAddress((void**)&hh,   g_h_h);
    cudaGetSymbolAddress((void**)&hl,   g_h_l);
    cudaGetSymbolAddress((void**)&wqh,  g_wqkv_h);
    cudaGetSymbolAddress((void**)&wql,  g_wqkv_l);
    cudaGetSymbolAddress((void**)&wph,  g_wproj_h);
    cudaGetSymbolAddress((void**)&wpl,  g_wproj_l);
    cudaGetSymbolAddress((void**)&wfh,  g_wfc_h);
    cudaGetSymbolAddress((void**)&wfl,  g_wfc_l);
    cudaGetSymbolAddress((void**)&wgh,  g_wfcp_h);
    cudaGetSymbolAddress((void**)&wgl,  g_wfcp_l);
    cudaGetSymbolAddress((void**)&wlh,  g_wlm_h);
    cudaGetSymbolAddress((void**)&wll,  g_wlm_l);

    cudaFuncSetAttribute(mma_gemm_kernel, cudaFuncAttributeMaxDynamicSharedMemorySize, SMEM_DYN);

    dim3 cb(32, 8);
    // weight convert + transpose (every call; deterministic)
    convw_kernel<<<dim3(C3 / 32,  C / 32,  LAYERS), cb>>>(attn_w,   wqh, wql, C,  C3,    C3);
    convw_kernel<<<dim3(C / 32,   C / 32,  LAYERS), cb>>>(proj_w,   wph, wpl, C,  C,     C);
    convw_kernel<<<dim3(C4 / 32,  C / 32,  LAYERS), cb>>>(fc_w,     wfh, wfl, C,  C4,    C4);
    convw_kernel<<<dim3(C / 32,   C4 / 32, LAYERS), cb>>>(fcproj_w, wgh, wgl, C4, C,     C);
    convw_kernel<<<dim3(VPAD / 32, C / 32, 1),      cb>>>(lm_head,  wlh, wll, C,  VOCAB, VPAD);

    embed_kernel<<<(NTOK * C + 255) / 256, 256>>>(idx, wte, wpe, x);

    const int MT = NTOK / 128;   // 16 M-tiles
    for (int l = 0; l < LAYERS; ++l) {
        ln_kernel<<<NTOK, 256>>>(x, ln1_w + l * C, ln1_b + l * C, lnh, lnl);
        mma_gemm_kernel<<<dim3(C3 / 128, MT), 256, SMEM_DYN>>>(
            lnh, lnl, wqh + (size_t)l * C3 * C, wql + (size_t)l * C3 * C,
            attn_b + (size_t)l * C3, nullptr, qkv, nullptr, nullptr, C3, C, 0);
        attn_kernel<<<dim3(TSEQ / QPB, BATCH * NH), 128>>>(qkv, atth, attl);
        mma_gemm_kernel<<<dim3(C / 128, MT), 256, SMEM_DYN>>>(
            atth, attl, wph + (size_t)l * C * C, wpl + (size_t)l * C * C,
            proj_b + (size_t)l * C, x, x, nullptr, nullptr, C, C, 2);
        ln_kernel<<<NTOK, 256>>>(x, ln2_w + l * C, ln2_b + l * C, lnh, lnl);
        mma_gemm_kernel<<<dim3(C4 / 128, MT), 256, SMEM_DYN>>>(
            lnh, lnl, wfh + (size_t)l * C4 * C, wfl + (size_t)l * C4 * C,
            fc_b + (size_t)l * C4, nullptr, nullptr, hh, hl, C4, C, 1);
        mma_gemm_kernel<<<dim3(C / 128, MT), 256, SMEM_DYN>>>(
            hh, hl, wgh + (size_t)l * C * C4, wgl + (size_t)l * C * C4,
            fcproj_b + (size_t)l * C, x, x, nullptr, nullptr, C, C4, 2);
    }

    ln_kernel<<<NTOK, 256>>>(x, lnf_w, lnf_b, lnh, lnl);
    mma_gemm_kernel<<<dim3(VPAD / 128, MT), 256, SMEM_DYN>>>(
        lnh, lnl, wlh, wll, nullptr, nullptr, out, nullptr, nullptr, VOCAB, C, 0);
}

// round 12
// speedup vs baseline: 2.3153x; 1.1537x over previous
#include <cuda_runtime.h>
#include <cuda_fp16.h>
#include <cuda_bf16.h>
#include <math.h>
#include <stdint.h>

// ---------------- GPT-2 small config ----------------
#define LAYERS 12
#define NH     12
#define C      768
#define HD     64
#define TSEQ   1024
#define BATCH  2
#define NTOK   (BATCH * TSEQ)      // 2048
#define VOCAB  50257
#define VPAD   50304               // VOCAB padded to 128
#define C3     (3 * C)             // 2304
#define C4     (4 * C)             // 3072

typedef unsigned long long ull;

// ---------------- packed fp32x2 helpers ----------------
__device__ __forceinline__ ull fma2(ull a, ull b, ull c) {
    ull d; asm("fma.rn.f32x2 %0, %1, %2, %3;" : "=l"(d) : "l"(a), "l"(b), "l"(c)); return d;
}
__device__ __forceinline__ ull mul2(ull a, ull b) {
    ull d; asm("mul.rn.f32x2 %0, %1, %2;" : "=l"(d) : "l"(a), "l"(b)); return d;
}
__device__ __forceinline__ ull pack2(float lo, float hi) {
    ull d; asm("mov.b64 %0, {%1, %2};" : "=l"(d) : "r"(__float_as_uint(lo)), "r"(__float_as_uint(hi))); return d;
}
__device__ __forceinline__ float2 unpack2(ull v) {
    unsigned lo, hi; asm("mov.b64 {%0, %1}, %2;" : "=r"(lo), "=r"(hi) : "l"(v));
    return make_float2(__uint_as_float(lo), __uint_as_float(hi));
}

__device__ __forceinline__ uint32_t smem_u32(const void* p) {
    uint32_t a;
    asm("{ .reg .u64 t; cvta.to.shared.u64 t, %1; cvt.u32.u64 %0, t; }" : "=r"(a) : "l"(p));
    return a;
}

__device__ __forceinline__ void split_f16(float v, __half* h, __half* l) {
    __half hi = __float2half(v);
    *h = hi;
    *l = __float2half(v - __half2float(hi));
}

// ---------------- mma.sync + cp.async helpers (sm_80 baseline) ----------------
__device__ __forceinline__ void ldsm_x4(uint32_t* r, uint32_t addr) {
    asm volatile("ldmatrix.sync.aligned.m8n8.x4.shared.b16 {%0,%1,%2,%3}, [%4];"
                 : "=r"(r[0]), "=r"(r[1]), "=r"(r[2]), "=r"(r[3]) : "r"(addr));
}
__device__ __forceinline__ void ldsm_x2(uint32_t* r, uint32_t addr) {
    asm volatile("ldmatrix.sync.aligned.m8n8.x2.shared.b16 {%0,%1}, [%2];"
                 : "=r"(r[0]), "=r"(r[1]) : "r"(addr));
}
__device__ __forceinline__ void mma_f16(float* c, const uint32_t* a, const uint32_t* b) {
    asm volatile(
        "mma.sync.aligned.m16n8k16.row.col.f32.f16.f16.f32 "
        "{%0,%1,%2,%3}, {%4,%5,%6,%7}, {%8,%9}, {%0,%1,%2,%3};"
        : "+f"(c[0]), "+f"(c[1]), "+f"(c[2]), "+f"(c[3])
        : "r"(a[0]), "r"(a[1]), "r"(a[2]), "r"(a[3]), "r"(b[0]), "r"(b[1]));
}
__device__ __forceinline__ void cp16(uint32_t dst, const void* src) {
    asm volatile("cp.async.cg.shared.global [%0], [%1], 16;" :: "r"(dst), "l"(src));
}
__device__ __forceinline__ void cp_commit() {
    asm volatile("cp.async.commit_group;" ::: "memory");
}

// ---------------- scratch (static __device__, no allocation) ----------------
__device__ float g_x  [NTOK * C];            // residual stream (fp32)
__device__ float g_qkv[NTOK * C3];           // qkv projection (fp32)
__device__ __half g_ln_h [NTOK * C],  g_ln_l [NTOK * C];
__device__ __half g_att_h[NTOK * C],  g_att_l[NTOK * C];
__device__ __half g_h_h  [NTOK * C4], g_h_l  [NTOK * C4];
// transposed fp16 weights: [N, K] row-major (single term; activations carry the split)
__device__ __half g_wqkv[LAYERS * C3 * C];
__device__ __half g_wproj[LAYERS * C * C];
__device__ __half g_wfc [LAYERS * C4 * C];
__device__ __half g_wfcp[LAYERS * C * C4];
__device__ __half g_wlm [VPAD * C];

// ---------------- weight convert + transpose: W[L,K,N] -> Wt[L,Npad,K] fp16 ----------------
__global__ void convw_kernel(const float* __restrict__ W,
                             __half* __restrict__ Th,
                             int K, int N, int Npad) {
    __shared__ float t[32][33];
    int l = blockIdx.z;
    int n0 = blockIdx.x * 32, k0 = blockIdx.y * 32;
    int tx = threadIdx.x, ty = threadIdx.y;    // 32 x 8
    const float* Wl = W + (size_t)l * K * N;
#pragma unroll
    for (int i = 0; i < 4; ++i) {
        int k = k0 + ty + i * 8;
        int n = n0 + tx;
        t[ty + i * 8][tx] = (n < N) ? Wl[(size_t)k * N + n] : 0.f;
    }
    __syncthreads();
    size_t obase = (size_t)l * Npad * K;
#pragma unroll
    for (int i = 0; i < 4; ++i) {
        int nl = ty + i * 8;
        Th[obase + (size_t)(n0 + nl) * K + k0 + tx] = __float2half(t[tx][nl]);
    }
}

// ---------------- embedding ----------------
__global__ void embed_kernel(const int* __restrict__ idx,
                             const float* __restrict__ wte,
                             const float* __restrict__ wpe,
                             float* __restrict__ x) {
    int i = blockIdx.x * blockDim.x + threadIdx.x;
    if (i >= NTOK * C) return;
    int c  = i % C;
    int bt = i / C;
    int t  = bt % TSEQ;
    x[i] = wte[(size_t)idx[bt] * C + c] + wpe[(size_t)t * C + c];
}

// ---------------- layernorm -> split fp16 ----------------
__global__ void ln_kernel(const float* __restrict__ in,
                          const float* __restrict__ w,
                          const float* __restrict__ b,
                          __half* __restrict__ out_h,
                          __half* __restrict__ out_l) {
    int row = blockIdx.x;
    int tid = threadIdx.x;                 // 256 threads
    const float* p = in + (size_t)row * C;

    float v[3];
    float s1 = 0.f, s2 = 0.f;
#pragma unroll
    for (int i = 0; i < 3; ++i) {
        v[i] = p[tid + i * 256];
        s1 += v[i];
        s2 += v[i] * v[i];
    }
#pragma unroll
    for (int o = 16; o > 0; o >>= 1) {
        s1 += __shfl_xor_sync(0xFFFFFFFFu, s1, o);
        s2 += __shfl_xor_sync(0xFFFFFFFFu, s2, o);
    }
    __shared__ float r1[8], r2[8];
    __shared__ float s_mu, s_rstd;
    int lane = tid & 31, warp = tid >> 5;
    if (lane == 0) { r1[warp] = s1; r2[warp] = s2; }
    __syncthreads();
    if (tid == 0) {
        float a = 0.f, q = 0.f;
#pragma unroll
        for (int i = 0; i < 8; ++i) { a += r1[i]; q += r2[i]; }
        float mu  = a / (float)C;
        float var = q / (float)C - mu * mu;
        s_mu   = mu;
        s_rstd = rsqrtf(var + 1e-5f);
    }
    __syncthreads();
    float mu = s_mu, rstd = s_rstd;
#pragma unroll
    for (int i = 0; i < 3; ++i) {
        int c = tid + i * 256;
        float o = (v[i] - mu) * rstd * w[c] + b[c];
        __half h, lo;
        split_f16(o, &h, &lo);
        out_h[(size_t)row * C + c] = h;
        out_l[(size_t)row * C + c] = lo;
    }
}

// ---------------- mma.sync GEMM, 2-stage cp.async pipeline, BK=64 ----------------
// D[M=2048, N] = (Ah+Al)[M,K] @ W^T  (W is [N,K] row-major fp16).
// 2-term activation split: ah*w + al*w, fp32 accumulation.
// epi: 0 = bias+store fp32, 1 = bias+GELU -> split fp16, 2 = bias+residual -> fp32
// CTA tile 128x128, BK=64, 8 warps in 2(M)x4(N); warp tile 64x32. Term-major MMA order.
#define PAD2 72                        // smem row stride in fp16 (144B): conflict-free ldmatrix
#define ARR_B   (128 * PAD2 * 2)       // bytes per tile array (18432)
#define STAGE_B (3 * ARR_B)            // bytes per stage (55296)
#define SMEM_DYN (2 * STAGE_B)         // 110592

__global__ __launch_bounds__(256)
void mma_gemm_kernel(const __half* __restrict__ Ah, const __half* __restrict__ Al,
                     const __half* __restrict__ Bw,
                     const float* __restrict__ bias, const float* __restrict__ res,
                     float* __restrict__ outf,
                     __half* __restrict__ oh, __half* __restrict__ ol,
                     int N, int K, int epi)
{
    extern __shared__ char dsm[];
    uint32_t sb = smem_u32(dsm);

    int tid = threadIdx.x, wid = tid >> 5, lane = tid & 31;
    int n0 = blockIdx.x * 128, m0 = blockIdx.y * 128;
    int wm = (wid & 1) * 64;     // warp M offset
    int wn = (wid >> 1) * 32;    // warp N offset

    float acc[4][4][4];
#pragma unroll
    for (int i = 0; i < 4; ++i)
#pragma unroll
        for (int j = 0; j < 4; ++j)
#pragma unroll
            for (int r = 0; r < 4; ++r) acc[i][j][r] = 0.f;

    // ldmatrix source byte offsets within a stage
    uint32_t oA = ((wm + (lane & 15)) * PAD2 + ((lane >> 4) << 3)) * 2;
    uint32_t oB = ((wn + (lane & 7)) * PAD2 + (((lane >> 3) & 1) << 3)) * 2;

    int nch = K >> 6;   // BK=64 chunks

    // issue cp.async loads of chunk c into stage s: 128 rows x 64 fp16 per array
    auto load_chunk = [&](int c, int s) {
        int k0 = c << 6;
        uint32_t stb = sb + s * STAGE_B;
#pragma unroll
        for (int i = 0; i < 4; ++i) {
            int idx = tid + (i << 8);        // 0..1023
            int row = idx >> 3;              // 0..127
            int c8  = (idx & 7) << 3;        // element col 0,8,..,56
            size_t ga = (size_t)(m0 + row) * K + k0 + c8;
            size_t gb = (size_t)(n0 + row) * K + k0 + c8;
            uint32_t so = (uint32_t)(row * PAD2 + c8) * 2;
            cp16(stb + 0 * ARR_B + so, Ah + ga);
            cp16(stb + 1 * ARR_B + so, Al + ga);
            cp16(stb + 2 * ARR_B + so, Bw + gb);
        }
    };

    load_chunk(0, 0);
    cp_commit();

    for (int c = 0; c < nch; ++c) {
        if (c + 1 < nch) { load_chunk(c + 1, (c + 1) & 1); cp_commit(); }
        if (c + 1 < nch) asm volatile("cp.async.wait_group 1;" ::: "memory");
        else             asm volatile("cp.async.wait_group 0;" ::: "memory");
        __syncthreads();

        uint32_t stb = sb + (c & 1) * STAGE_B;
        uint32_t aAh = stb + 0 * ARR_B + oA;
        uint32_t aAl = stb + 1 * ARR_B + oA;
        uint32_t aB  = stb + 2 * ARR_B + oB;

#pragma unroll
        for (int ks = 0; ks < 4; ++ks) {
            uint32_t koff = ks * 16 * 2;   // byte offset for k slice
            uint32_t bw[4][2];
#pragma unroll
            for (int ni = 0; ni < 4; ++ni)
                ldsm_x2(bw[ni], aB + ni * 8 * PAD2 * 2 + koff);
            uint32_t ah[4][4], al[4][4];
#pragma unroll
            for (int mi = 0; mi < 4; ++mi) {
                ldsm_x4(ah[mi], aAh + mi * 16 * PAD2 * 2 + koff);
                ldsm_x4(al[mi], aAl + mi * 16 * PAD2 * 2 + koff);
            }
            // term-major: 16 independent MMAs per term (acc reuse distance = 16)
#pragma unroll
            for (int mi = 0; mi < 4; ++mi)
#pragma unroll
                for (int ni = 0; ni < 4; ++ni)
                    mma_f16(acc[mi][ni], ah[mi], bw[ni]);
#pragma unroll
            for (int mi = 0; mi < 4; ++mi)
#pragma unroll
                for (int ni = 0; ni < 4; ++ni)
                    mma_f16(acc[mi][ni], al[mi], bw[ni]);
        }
        __syncthreads();
    }

    // epilogue: acc frag c0:(r,c) c1:(r,c+1) c2:(r+8,c) c3:(r+8,c+1); r=lane/4, c=2*(lane%4)
#pragma unroll
    for (int mi = 0; mi < 4; ++mi) {
#pragma unroll
        for (int ni = 0; ni < 4; ++ni) {
            int m = m0 + wm + mi * 16 + (lane >> 2);
            int n = n0 + wn + ni * 8 + ((lane & 3) << 1);
#pragma unroll
            for (int half = 0; half < 2; ++half) {
                int mm = m + half * 8;
#pragma unroll
                for (int s = 0; s < 2; ++s) {
                    int nn = n + s;
                    if (nn < N) {
                        float v = acc[mi][ni][half * 2 + s] + (bias ? bias[nn] : 0.f);
                        size_t o = (size_t)mm * N + nn;
                        if (epi == 0) {
                            outf[o] = v;
                        } else if (epi == 1) {
                            v = 0.5f * v * (1.f + tanhf(0.7978845608028654f * (v + 0.044715f * v * v * v)));
                            __half h, lo;
                            split_f16(v, &h, &lo);
                            oh[o] = h; ol[o] = lo;
                        } else {
                            outf[o] = v + res[o];
                        }
                    }
                }
            }
        }
    }
}

// ---------------- causal attention: 4 threads per query, smem K/V tiles ----------------
#define QPB 32     // queries per block (128 threads / 4)
#define KT  16     // keys per smem tile

__global__ __launch_bounds__(128) void attn_kernel(const float* __restrict__ qkv,
                                                   __half* __restrict__ out_h,
                                                   __half* __restrict__ out_l) {
    __shared__ float Ks[KT][HD];
    __shared__ float Vs[KT][HD];

    int tid = threadIdx.x;
    int g   = tid & 3;                      // dim-slice 0..3 (16 dims each)
    int qi  = tid >> 2;                     // query within block 0..31
    int qt  = gridDim.x - 1 - blockIdx.x;   // heaviest q-tiles first
    int q   = qt * QPB + qi;
    int bh  = blockIdx.y;
    int b   = bh / NH, h = bh % NH;
    int d0  = g * 16;                       // first dim this thread owns

    const float* base = qkv + (size_t)b * TSEQ * C3 + h * HD;

    // load this thread's 16 query dims (scaled by 1/sqrt(HD))
    ull q2[8];
    {
        const ulonglong2* qp = (const ulonglong2*)(base + (size_t)q * C3 + d0);
        ull scale = pack2(0.125f, 0.125f);
#pragma unroll
        for (int i = 0; i < 4; ++i) {
            ulonglong2 v = qp[i];
            q2[2 * i + 0] = mul2(v.x, scale);
            q2[2 * i + 1] = mul2(v.y, scale);
        }
    }

    ull acc2[8];
#pragma unroll
    for (int i = 0; i < 8; ++i) acc2[i] = 0ULL;
    float m = -3e38f, l = 0.f;

    int ntiles = (qt * QPB + QPB - 1) / KT + 1;
    for (int t = 0; t < ntiles; ++t) {
        int k0 = t * KT;
        __syncthreads();
#pragma unroll
        for (int i = 0; i < 2; ++i) {
            int idx = tid + i * 128;
            int k  = idx >> 4;
            int d4 = (idx & 15) * 4;
            const float* row = base + (size_t)(k0 + k) * C3;
            *(float4*)&Ks[k][d4] = *(const float4*)(row + C + d4);
            *(float4*)&Vs[k][d4] = *(const float4*)(row + 2 * C + d4);
        }
        __syncthreads();

        float s[KT];
#pragma unroll
        for (int k = 0; k < KT; ++k) {
            const ulonglong2* kp = (const ulonglong2*)&Ks[k][d0];
            ull sa = 0ULL, sb2 = 0ULL;
#pragma unroll
            for (int d = 0; d < 4; ++d) {
                ulonglong2 kv = kp[d];
                sa  = fma2(q2[2 * d + 0], kv.x, sa);
                sb2 = fma2(q2[2 * d + 1], kv.y, sb2);
            }
            float2 ua = unpack2(sa);
            float2 ub = unpack2(sb2);
            float sp = (ua.x + ua.y) + (ub.x + ub.y);
            sp += __shfl_xor_sync(0xFFFFFFFFu, sp, 1);
            sp += __shfl_xor_sync(0xFFFFFFFFu, sp, 2);
            s[k] = sp;
        }

        float mt = -3e38f;
#pragma unroll
        for (int k = 0; k < KT; ++k)
            if (k0 + k <= q) mt = fmaxf(mt, s[k]);
        float mn = fmaxf(m, mt);
        float alpha = __expf(m - mn);
        ull al2 = pack2(alpha, alpha);
#pragma unroll
        for (int d = 0; d < 8; ++d) acc2[d] = mul2(acc2[d], al2);
        l *= alpha;
#pragma unroll
        for (int k = 0; k < KT; ++k) {
            float p = (k0 + k <= q) ? __expf(s[k] - mn) : 0.f;
            l += p;
            ull p2 = pack2(p, p);
            const ulonglong2* vp = (const ulonglong2*)&Vs[k][d0];
#pragma unroll
            for (int d = 0; d < 4; ++d) {
                ulonglong2 vv = vp[d];
                acc2[2 * d + 0] = fma2(p2, vv.x, acc2[2 * d + 0]);
                acc2[2 * d + 1] = fma2(p2, vv.y, acc2[2 * d + 1]);
            }
        }
        m = mn;
    }

    float inv = 1.f / l;
    size_t ob = (size_t)(b * TSEQ + q) * C + h * HD + d0;
#pragma unroll
    for (int d = 0; d < 8; ++d) {
        float2 u = unpack2(acc2[d]);
        __half h0, l0, h1, l1;
        split_f16(u.x * inv, &h0, &l0);
        split_f16(u.y * inv, &h1, &l1);
        out_h[ob + 2 * d + 0] = h0;  out_l[ob + 2 * d + 0] = l0;
        out_h[ob + 2 * d + 1] = h1;  out_l[ob + 2 * d + 1] = l1;
    }
}

// ---------------- launch ----------------
extern "C" void kernel_launch(void* const* d_in, const int* in_sizes, int n_in,
                              void* d_out, int out_size) {
    const int*   idx      = (const int*)  d_in[0];
    const float* wte      = (const float*)d_in[1];
    const float* wpe      = (const float*)d_in[2];
    const float* ln1_w    = (const float*)d_in[3];
    const float* ln1_b    = (const float*)d_in[4];
    const float* attn_w   = (const float*)d_in[5];
    const float* attn_b   = (const float*)d_in[6];
    const float* proj_w   = (const float*)d_in[7];
    const float* proj_b   = (const float*)d_in[8];
    const float* ln2_w    = (const float*)d_in[9];
    const float* ln2_b    = (const float*)d_in[10];
    const float* fc_w     = (const float*)d_in[11];
    const float* fc_b     = (const float*)d_in[12];
    const float* fcproj_w = (const float*)d_in[13];
    const float* fcproj_b = (const float*)d_in[14];
    const float* lnf_w    = (const float*)d_in[15];
    const float* lnf_b    = (const float*)d_in[16];
    const float* lm_head  = (const float*)d_in[17];
    float* out = (float*)d_out;

    float *x, *qkv;
    __half *lnh, *lnl, *atth, *attl, *hh, *hl;
    __half *wq, *wp, *wf, *wg, *wl;
    cudaGetSymbolAddress((void**)&x,    g_x);
    cudaGetSymbolAddress((void**)&qkv,  g_qkv);
    cudaGetSymbolAddress((void**)&lnh,  g_ln_h);
    cudaGetSymbolAddress((void**)&lnl,  g_ln_l);
    cudaGetSymbolAddress((void**)&atth, g_att_h);
    cudaGetSymbolAddress((void**)&attl, g_att_l);
    cudaGetSymbolAddress((void**)&hh,   g_h_h);
    cudaGetSymbolAddress((void**)&hl,   g_h_l);
    cudaGetSymbolAddress((void**)&wq,   g_wqkv);
    cudaGetSymbolAddress((void**)&wp,   g_wproj);
    cudaGetSymbolAddress((void**)&wf,   g_wfc);
    cudaGetSymbolAddress((void**)&wg,   g_wfcp);
    cudaGetSymbolAddress((void**)&wl,   g_wlm);

    cudaFuncSetAttribute(mma_gemm_kernel, cudaFuncAttributeMaxDynamicSharedMemorySize, SMEM_DYN);

    dim3 cb(32, 8);
    // weight convert + transpose (every call; deterministic)
    convw_kernel<<<dim3(C3 / 32,  C / 32,  LAYERS), cb>>>(attn_w,   wq, C,  C3,    C3);
    convw_kernel<<<dim3(C / 32,   C / 32,  LAYERS), cb>>>(proj_w,   wp, C,  C,     C);
    convw_kernel<<<dim3(C4 / 32,  C / 32,  LAYERS), cb>>>(fc_w,     wf, C,  C4,    C4);
    convw_kernel<<<dim3(C / 32,   C4 / 32, LAYERS), cb>>>(fcproj_w, wg, C4, C,     C);
    convw_kernel<<<dim3(VPAD / 32, C / 32, 1),      cb>>>(lm_head,  wl, C,  VOCAB, VPAD);

    embed_kernel<<<(NTOK * C + 255) / 256, 256>>>(idx, wte, wpe, x);

    const int MT = NTOK / 128;   // 16 M-tiles
    for (int l = 0; l < LAYERS; ++l) {
        ln_kernel<<<NTOK, 256>>>(x, ln1_w + l * C, ln1_b + l * C, lnh, lnl);
        mma_gemm_kernel<<<dim3(C3 / 128, MT), 256, SMEM_DYN>>>(
            lnh, lnl, wq + (size_t)l * C3 * C,
            attn_b + (size_t)l * C3, nullptr, qkv, nullptr, nullptr, C3, C, 0);
        attn_kernel<<<dim3(TSEQ / QPB, BATCH * NH), 128>>>(qkv, atth, attl);
        mma_gemm_kernel<<<dim3(C / 128, MT), 256, SMEM_DYN>>>(
            atth, attl, wp + (size_t)l * C * C,
            proj_b + (size_t)l * C, x, x, nullptr, nullptr, C, C, 2);
        ln_kernel<<<NTOK, 256>>>(x, ln2_w + l * C, ln2_b + l * C, lnh, lnl);
        mma_gemm_kernel<<<dim3(C4 / 128, MT), 256, SMEM_DYN>>>(
            lnh, lnl, wf + (size_t)l * C4 * C,
            fc_b + (size_t)l * C4, nullptr, nullptr, hh, hl, C4, C, 1);
        mma_gemm_kernel<<<dim3(C / 128, MT), 256, SMEM_DYN>>>(
            hh, hl, wg + (size_t)l * C * C4,
            fcproj_b + (size_t)l * C, x, x, nullptr, nullptr, C, C4, 2);
    }

    ln_kernel<<<NTOK, 256>>>(x, lnf_w, lnf_b, lnh, lnl);
    mma_gemm_kernel<<<dim3(VPAD / 128, MT), 256, SMEM_DYN>>>(
        lnh, lnl, wl, nullptr, nullptr, out, nullptr, nullptr, VOCAB, C, 0);
}